// round 14
// baseline (speedup 1.0000x reference)
#include <cuda_runtime.h>
#include <cuda_bf16.h>
#include <stdint.h>

#define TT 2048
#define DD 64
#define HH 16
#define BB 2

__device__ float g_m[BB*HH*TT];
__device__ float g_inv[BB*HH*TT];

__device__ __forceinline__ void mma16816(float4& d, const uint32_t* a,
                                         uint32_t b0, uint32_t b1) {
    asm volatile("mma.sync.aligned.m16n8k16.row.col.f32.bf16.bf16.f32 "
        "{%0,%1,%2,%3}, {%4,%5,%6,%7}, {%8,%9}, {%0,%1,%2,%3};"
        : "+f"(d.x), "+f"(d.y), "+f"(d.z), "+f"(d.w)
        : "r"(a[0]), "r"(a[1]), "r"(a[2]), "r"(a[3]), "r"(b0), "r"(b1));
}
__device__ __forceinline__ void cvt_hilo2(float x, float y, uint32_t& hi, uint32_t& lo) {
    __nv_bfloat162 hb = __floats2bfloat162_rn(x, y);
    __nv_bfloat162 lb = __floats2bfloat162_rn(x - __bfloat162float(hb.x),
                                              y - __bfloat162float(hb.y));
    hi = *reinterpret_cast<uint32_t*>(&hb);
    lo = *reinterpret_cast<uint32_t*>(&lb);
}

// ==================== Kernel A: QK^T stats only (no score write) ====================
#define A_KHI 0
#define A_KLO 18432
#define A_MASK 36864
#define A_TOTAL 45056

__global__ __launch_bounds__(256, 2)
void qk_stats(const float* __restrict__ gq, const float* __restrict__ gk,
              const int* __restrict__ gmask, const float* __restrict__ gbias)
{
    extern __shared__ char sm[];
    char* s_khi = sm + A_KHI;
    char* s_klo = sm + A_KLO;
    int*  s_mask = (int*)(sm + A_MASK);

    const int t = threadIdx.x, wid = t >> 5, lane = t & 31;
    const int h = blockIdx.y, b = blockIdx.z;
    const int q0 = blockIdx.x * 128;
    const int g = lane >> 2, qd = lane & 3;
    const int lr = wid*16 + g;

    const float* qb = gq + (((size_t)(b*HH + h))*TT + q0)*DD;
    const float* kb = gk + ((size_t)(b*HH + h))*TT*DD;
    const float* bbp = gbias + ((size_t)h*TT + q0)*TT;

    ((int4*)s_mask)[t*2]   = ((const int4*)(gmask + b*TT))[t*2];
    ((int4*)s_mask)[t*2+1] = ((const int4*)(gmask + b*TT))[t*2+1];

    uint32_t ah[4][4], al[4][4];
    {
        const float* r0p = qb + (size_t)lr*DD;
        const float* r1p = qb + (size_t)(lr+8)*DD;
        #pragma unroll
        for (int ks = 0; ks < 4; ++ks) {
            const int c0 = ks*16 + qd*2;
            float2 x00 = *(const float2*)(r0p + c0);
            float2 x02 = *(const float2*)(r0p + c0 + 8);
            float2 x10 = *(const float2*)(r1p + c0);
            float2 x12 = *(const float2*)(r1p + c0 + 8);
            cvt_hilo2(x00.x*0.125f, x00.y*0.125f, ah[ks][0], al[ks][0]);
            cvt_hilo2(x10.x*0.125f, x10.y*0.125f, ah[ks][1], al[ks][1]);
            cvt_hilo2(x02.x*0.125f, x02.y*0.125f, ah[ks][2], al[ks][2]);
            cvt_hilo2(x12.x*0.125f, x12.y*0.125f, ah[ks][3], al[ks][3]);
        }
    }

    const int key = t >> 1, half = t & 1;
    const float* ksrc = kb + (size_t)key*DD + half*32;

    float4 kraw[8];
    #pragma unroll
    for (int ch = 0; ch < 8; ++ch) kraw[ch] = ((const float4*)ksrc)[ch];

    float m0 = -3.4e38f, s0 = 0.f, m1 = -3.4e38f, s1 = 0.f;

    for (int j = 0; j < 16; ++j) {
        __syncthreads();
        #pragma unroll
        for (int ch = 0; ch < 4; ++ch) {
            float4 a = kraw[2*ch];
            float4 c = kraw[2*ch+1];
            uint32_t h0,l0,h1,l1,h2,l2,h3,l3;
            cvt_hilo2(a.x,a.y,h0,l0); cvt_hilo2(a.z,a.w,h1,l1);
            cvt_hilo2(c.x,c.y,h2,l2); cvt_hilo2(c.z,c.w,h3,l3);
            const int off = key*144 + half*64 + ch*16;
            *(uint4*)(s_khi + off) = make_uint4(h0,h1,h2,h3);
            *(uint4*)(s_klo + off) = make_uint4(l0,l1,l2,l3);
        }
        __syncthreads();

        if (j + 1 < 16) {
            const float* nsrc = ksrc + (size_t)(j+1)*128*DD;
            #pragma unroll
            for (int ch = 0; ch < 8; ++ch) kraw[ch] = ((const float4*)nsrc)[ch];
        }

        float2 bi0 = *(const float2*)(bbp + (size_t)lr*TT + j*128 + qd*2);
        float2 bi1 = *(const float2*)(bbp + (size_t)(lr+8)*TT + j*128 + qd*2);

        #pragma unroll 2
        for (int n = 0; n < 16; ++n) {
            float2 nbi0, nbi1;
            if (n + 1 < 16) {
                const int cn = j*128 + (n+1)*8 + qd*2;
                nbi0 = *(const float2*)(bbp + (size_t)lr*TT + cn);
                nbi1 = *(const float2*)(bbp + (size_t)(lr+8)*TT + cn);
            }
            float4 d = make_float4(0.f, 0.f, 0.f, 0.f);
            const int keyl = n*8 + g;
            const char* bhp = s_khi + keyl*144 + qd*4;
            const char* blp = s_klo + keyl*144 + qd*4;
            #pragma unroll
            for (int ks = 0; ks < 4; ++ks) {
                uint32_t bh0 = *(const uint32_t*)(bhp + ks*32);
                uint32_t bh1 = *(const uint32_t*)(bhp + ks*32 + 16);
                uint32_t bl0 = *(const uint32_t*)(blp + ks*32);
                uint32_t bl1 = *(const uint32_t*)(blp + ks*32 + 16);
                mma16816(d, ah[ks], bh0, bh1);
                mma16816(d, al[ks], bh0, bh1);
                mma16816(d, ah[ks], bl0, bl1);
            }
            const int c = j*128 + n*8 + qd*2;
            int2 mv = *(const int2*)&s_mask[c];
            float v00 = mv.x ? d.x + bi0.x : -1e9f;
            float v01 = mv.y ? d.y + bi0.y : -1e9f;
            float v10 = mv.x ? d.z + bi1.x : -1e9f;
            float v11 = mv.y ? d.w + bi1.y : -1e9f;
            float nm0 = fmaxf(m0, fmaxf(v00, v01));
            s0 = s0*__expf(m0 - nm0) + __expf(v00 - nm0) + __expf(v01 - nm0);
            m0 = nm0;
            float nm1 = fmaxf(m1, fmaxf(v10, v11));
            s1 = s1*__expf(m1 - nm1) + __expf(v10 - nm1) + __expf(v11 - nm1);
            m1 = nm1;
            bi0 = nbi0; bi1 = nbi1;
        }
    }

    #pragma unroll
    for (int o = 1; o < 4; o <<= 1) {
        float mo = __shfl_xor_sync(0xffffffffu, m0, o);
        float so = __shfl_xor_sync(0xffffffffu, s0, o);
        float nm = fmaxf(m0, mo);
        s0 = s0*__expf(m0 - nm) + so*__expf(mo - nm); m0 = nm;
        mo = __shfl_xor_sync(0xffffffffu, m1, o);
        so = __shfl_xor_sync(0xffffffffu, s1, o);
        nm = fmaxf(m1, mo);
        s1 = s1*__expf(m1 - nm) + so*__expf(mo - nm); m1 = nm;
    }
    if (qd == 0) {
        const size_t gi = (size_t)(b*HH + h)*TT + q0;
        g_m[gi + lr]       = m0;  g_inv[gi + lr]     = 1.f/s0;
        g_m[gi + lr + 8]   = m1;  g_inv[gi + lr + 8] = 1.f/s1;
    }
}

// ==================== Kernel B: fused QK-recompute + normalize + attn write + PV ====================
#define F_KHI 0            // 64 keys * 144 B
#define F_KLO 9216
#define F_VHI 18432        // 64 d-rows * 144 B
#define F_VLO 27648
#define F_MASK 36864       // 2048 ints
#define F_TOTAL 45056

__global__ __launch_bounds__(256, 2)
void fused_pv(const float* __restrict__ gq, const float* __restrict__ gk,
              const float* __restrict__ gv, const int* __restrict__ gmask,
              const float* __restrict__ gbias, float* __restrict__ gattn,
              float* __restrict__ gout)
{
    extern __shared__ char sm[];
    char* s_khi = sm + F_KHI;
    char* s_klo = sm + F_KLO;
    char* s_vhi = sm + F_VHI;
    char* s_vlo = sm + F_VLO;
    int*  s_mask = (int*)(sm + F_MASK);

    const int t = threadIdx.x, wid = t >> 5, lane = t & 31;
    const int h = blockIdx.y, b = blockIdx.z;
    const int q0 = blockIdx.x * 128;
    const int g = lane >> 2, qd = lane & 3;
    const int lr = wid*16 + g;

    const float* qb = gq + (((size_t)(b*HH + h))*TT + q0)*DD;
    const float* kb = gk + ((size_t)(b*HH + h))*TT*DD;
    const float* vb = gv + ((size_t)(b*HH + h))*TT*DD;
    const float* bbp = gbias + ((size_t)h*TT + q0)*TT;
    float*       ab = gattn + (((size_t)(b*HH + h))*TT + q0)*TT;

    ((int4*)s_mask)[t*2]   = ((const int4*)(gmask + b*TT))[t*2];
    ((int4*)s_mask)[t*2+1] = ((const int4*)(gmask + b*TT))[t*2+1];

    // Q frags (scale folded) — identical construction to kernel A
    uint32_t ah[4][4], al[4][4];
    {
        const float* r0p = qb + (size_t)lr*DD;
        const float* r1p = qb + (size_t)(lr+8)*DD;
        #pragma unroll
        for (int ks = 0; ks < 4; ++ks) {
            const int c0 = ks*16 + qd*2;
            float2 x00 = *(const float2*)(r0p + c0);
            float2 x02 = *(const float2*)(r0p + c0 + 8);
            float2 x10 = *(const float2*)(r1p + c0);
            float2 x12 = *(const float2*)(r1p + c0 + 8);
            cvt_hilo2(x00.x*0.125f, x00.y*0.125f, ah[ks][0], al[ks][0]);
            cvt_hilo2(x10.x*0.125f, x10.y*0.125f, ah[ks][1], al[ks][1]);
            cvt_hilo2(x02.x*0.125f, x02.y*0.125f, ah[ks][2], al[ks][2]);
            cvt_hilo2(x12.x*0.125f, x12.y*0.125f, ah[ks][3], al[ks][3]);
        }
    }

    const size_t st = (size_t)(b*HH + h)*TT + q0;
    const float m_0 = g_m[st + lr],     i_0 = g_inv[st + lr];
    const float m_1 = g_m[st + lr + 8], i_1 = g_inv[st + lr + 8];

    float4 o[8];
    #pragma unroll
    for (int i = 0; i < 8; ++i) o[i] = make_float4(0.f, 0.f, 0.f, 0.f);

    const int kkey = t >> 2, kqtr = t & 3;   // K staging: key 0..63, 16-float quarter
    const int vkp = lane,    vdq = wid;      // V staging: key pair, d-octet

    for (int j = 0; j < 32; ++j) {
        __syncthreads();
        // ---- stage K tile (64 keys x 64 d) hi/lo ----
        {
            const float* src = kb + (size_t)(j*64 + kkey)*DD + kqtr*16;
            float4 f0 = ((const float4*)src)[0];
            float4 f1 = ((const float4*)src)[1];
            float4 f2 = ((const float4*)src)[2];
            float4 f3 = ((const float4*)src)[3];
            uint32_t hh[8], ll[8];
            cvt_hilo2(f0.x,f0.y,hh[0],ll[0]); cvt_hilo2(f0.z,f0.w,hh[1],ll[1]);
            cvt_hilo2(f1.x,f1.y,hh[2],ll[2]); cvt_hilo2(f1.z,f1.w,hh[3],ll[3]);
            cvt_hilo2(f2.x,f2.y,hh[4],ll[4]); cvt_hilo2(f2.z,f2.w,hh[5],ll[5]);
            cvt_hilo2(f3.x,f3.y,hh[6],ll[6]); cvt_hilo2(f3.z,f3.w,hh[7],ll[7]);
            const int off = kkey*144 + kqtr*32;
            *(uint4*)(s_khi + off)      = make_uint4(hh[0],hh[1],hh[2],hh[3]);
            *(uint4*)(s_khi + off + 16) = make_uint4(hh[4],hh[5],hh[6],hh[7]);
            *(uint4*)(s_klo + off)      = make_uint4(ll[0],ll[1],ll[2],ll[3]);
            *(uint4*)(s_klo + off + 16) = make_uint4(ll[4],ll[5],ll[6],ll[7]);
        }
        // ---- stage V^T tile (64 keys) hi/lo ----
        {
            const float* v0 = vb + (size_t)(j*64 + 2*vkp)*DD + vdq*8;
            float4 a0 = *(const float4*)v0;
            float4 a1 = *(const float4*)(v0 + 4);
            float4 c0 = *(const float4*)(v0 + DD);
            float4 c1 = *(const float4*)(v0 + DD + 4);
            #pragma unroll
            for (int u = 0; u < 4; ++u) {
                float x = (u==0)?a0.x:(u==1)?a0.y:(u==2)?a0.z:a0.w;
                float y = (u==0)?c0.x:(u==1)?c0.y:(u==2)?c0.z:c0.w;
                uint32_t hp, lp;
                cvt_hilo2(x, y, hp, lp);
                const int off = (vdq*8 + u)*144 + vkp*4;
                *(uint32_t*)(s_vhi + off) = hp;
                *(uint32_t*)(s_vlo + off) = lp;
            }
            #pragma unroll
            for (int u = 0; u < 4; ++u) {
                float x = (u==0)?a1.x:(u==1)?a1.y:(u==2)?a1.z:a1.w;
                float y = (u==0)?c1.x:(u==1)?c1.y:(u==2)?c1.z:c1.w;
                uint32_t hp, lp;
                cvt_hilo2(x, y, hp, lp);
                const int off = (vdq*8 + 4 + u)*144 + vkp*4;
                *(uint32_t*)(s_vhi + off) = hp;
                *(uint32_t*)(s_vlo + off) = lp;
            }
        }
        __syncthreads();

        // ---- QK recompute + epilogue -> P frags in registers + final attn write ----
        uint32_t pfh[8][2], pfl[8][2];
        float2 bi0 = *(const float2*)(bbp + (size_t)lr*TT + j*64 + qd*2);
        float2 bi1 = *(const float2*)(bbp + (size_t)(lr+8)*TT + j*64 + qd*2);
        #pragma unroll
        for (int n = 0; n < 8; ++n) {
            float2 nbi0, nbi1;
            if (n + 1 < 8) {
                const int cn = j*64 + (n+1)*8 + qd*2;
                nbi0 = *(const float2*)(bbp + (size_t)lr*TT + cn);
                nbi1 = *(const float2*)(bbp + (size_t)(lr+8)*TT + cn);
            }
            float4 d = make_float4(0.f, 0.f, 0.f, 0.f);
            const int keyl = n*8 + g;
            const char* bhp = s_khi + keyl*144 + qd*4;
            const char* blp = s_klo + keyl*144 + qd*4;
            #pragma unroll
            for (int ks = 0; ks < 4; ++ks) {
                uint32_t bh0 = *(const uint32_t*)(bhp + ks*32);
                uint32_t bh1 = *(const uint32_t*)(bhp + ks*32 + 16);
                uint32_t bl0 = *(const uint32_t*)(blp + ks*32);
                uint32_t bl1 = *(const uint32_t*)(blp + ks*32 + 16);
                mma16816(d, ah[ks], bh0, bh1);
                mma16816(d, al[ks], bh0, bh1);
                mma16816(d, ah[ks], bl0, bl1);
            }
            const int c = j*64 + n*8 + qd*2;
            int2 mv = *(const int2*)&s_mask[c];
            float v00 = mv.x ? d.x + bi0.x : -1e9f;
            float v01 = mv.y ? d.y + bi0.y : -1e9f;
            float v10 = mv.x ? d.z + bi1.x : -1e9f;
            float v11 = mv.y ? d.w + bi1.y : -1e9f;
            float p00 = __expf(v00 - m_0)*i_0;
            float p01 = __expf(v01 - m_0)*i_0;
            float p10 = __expf(v10 - m_1)*i_1;
            float p11 = __expf(v11 - m_1)*i_1;
            *(float2*)(ab + (size_t)lr*TT + c)     = make_float2(p00, p01);
            *(float2*)(ab + (size_t)(lr+8)*TT + c) = make_float2(p10, p11);
            cvt_hilo2(p00, p01, pfh[n][0], pfl[n][0]);
            cvt_hilo2(p10, p11, pfh[n][1], pfl[n][1]);
            bi0 = nbi0; bi1 = nbi1;
        }

        // ---- PV: P frags (regs) x V^T (smem) ----
        #pragma unroll
        for (int kst = 0; kst < 4; ++kst) {
            uint32_t ph[4] = { pfh[2*kst][0], pfh[2*kst][1],
                               pfh[2*kst+1][0], pfh[2*kst+1][1] };
            uint32_t pl[4] = { pfl[2*kst][0], pfl[2*kst][1],
                               pfl[2*kst+1][0], pfl[2*kst+1][1] };
            #pragma unroll
            for (int ns = 0; ns < 8; ++ns) {
                const int bbase = (ns*8 + g)*144 + kst*32 + qd*4;
                uint32_t bh0 = *(const uint32_t*)(s_vhi + bbase);
                uint32_t bh1 = *(const uint32_t*)(s_vhi + bbase + 16);
                uint32_t bl0 = *(const uint32_t*)(s_vlo + bbase);
                uint32_t bl1 = *(const uint32_t*)(s_vlo + bbase + 16);
                mma16816(o[ns], ph, bh0, bh1);
                mma16816(o[ns], pl, bh0, bh1);
                mma16816(o[ns], ph, bl0, bl1);
            }
        }
    }

    float* ob = gout + (((size_t)(b*HH + h))*TT + q0)*DD;
    #pragma unroll
    for (int ns = 0; ns < 8; ++ns) {
        const int c = ns*8 + qd*2;
        *(float2*)(ob + (size_t)lr*DD + c)     = make_float2(o[ns].x, o[ns].y);
        *(float2*)(ob + (size_t)(lr+8)*DD + c) = make_float2(o[ns].z, o[ns].w);
    }
}

extern "C" void kernel_launch(void* const* d_in, const int* in_sizes, int n_in,
                              void* d_out, int out_size)
{
    const float* q    = (const float*)d_in[0];
    const float* k    = (const float*)d_in[1];
    const float* v    = (const float*)d_in[2];
    const int*   mask = (const int*)d_in[3];
    const float* bias = (const float*)d_in[4];
    float* out  = (float*)d_out;
    float* attn = out + (long long)BB*HH*TT*DD;

    cudaFuncSetAttribute(qk_stats, cudaFuncAttributeMaxDynamicSharedMemorySize, A_TOTAL);
    cudaFuncSetAttribute(fused_pv, cudaFuncAttributeMaxDynamicSharedMemorySize, F_TOTAL);

    dim3 grid(TT/128, HH, BB);
    qk_stats<<<grid, 256, A_TOTAL>>>(q, k, mask, bias);
    fused_pv<<<grid, 256, F_TOTAL>>>(q, k, v, mask, bias, attn, out);
}

// round 15
// speedup vs baseline: 1.1820x; 1.1820x over previous
#include <cuda_runtime.h>
#include <cuda_bf16.h>
#include <stdint.h>

#define TT 2048
#define DD 64
#define HH 16
#define BB 2

__device__ float g_m[BB*HH*TT];
__device__ float g_inv[BB*HH*TT];

__device__ __forceinline__ void mma16816(float4& d, const uint32_t* a,
                                         uint32_t b0, uint32_t b1) {
    asm volatile("mma.sync.aligned.m16n8k16.row.col.f32.bf16.bf16.f32 "
        "{%0,%1,%2,%3}, {%4,%5,%6,%7}, {%8,%9}, {%0,%1,%2,%3};"
        : "+f"(d.x), "+f"(d.y), "+f"(d.z), "+f"(d.w)
        : "r"(a[0]), "r"(a[1]), "r"(a[2]), "r"(a[3]), "r"(b0), "r"(b1));
}
__device__ __forceinline__ void cvt_hilo2(float x, float y, uint32_t& hi, uint32_t& lo) {
    __nv_bfloat162 hb = __floats2bfloat162_rn(x, y);
    __nv_bfloat162 lb = __floats2bfloat162_rn(x - __bfloat162float(hb.x),
                                              y - __bfloat162float(hb.y));
    hi = *reinterpret_cast<uint32_t*>(&hb);
    lo = *reinterpret_cast<uint32_t*>(&lb);
}

// ==================== Kernel A: QK^T, double-buffered 64-key tiles ====================
// buf: KHI 64*144=9216 | KLO 9216  => 18432/buf, 2 bufs = 36864; mask 8192
#define A_BUF 18432
#define A_MASK 36864
#define A_TOTAL 45056

__global__ __launch_bounds__(256, 2)
void qk_mma(const float* __restrict__ gq, const float* __restrict__ gk,
            const int* __restrict__ gmask, const float* __restrict__ gbias,
            float* __restrict__ gattn)
{
    extern __shared__ char sm[];
    int* s_mask = (int*)(sm + A_MASK);

    const int t = threadIdx.x, wid = t >> 5, lane = t & 31;
    const int h = blockIdx.y, b = blockIdx.z;
    const int q0 = blockIdx.x * 128;
    const int g = lane >> 2, qd = lane & 3;
    const int lr = wid*16 + g;

    const float* qb = gq + (((size_t)(b*HH + h))*TT + q0)*DD;
    const float* kb = gk + ((size_t)(b*HH + h))*TT*DD;
    const float* bbp = gbias + ((size_t)h*TT + q0)*TT;
    float*       ab = gattn + (((size_t)(b*HH + h))*TT + q0)*TT;

    ((int4*)s_mask)[t*2]   = ((const int4*)(gmask + b*TT))[t*2];
    ((int4*)s_mask)[t*2+1] = ((const int4*)(gmask + b*TT))[t*2+1];

    // Q frags (scale folded)
    uint32_t ah[4][4], al[4][4];
    {
        const float* r0p = qb + (size_t)lr*DD;
        const float* r1p = qb + (size_t)(lr+8)*DD;
        #pragma unroll
        for (int ks = 0; ks < 4; ++ks) {
            const int c0 = ks*16 + qd*2;
            float2 x00 = *(const float2*)(r0p + c0);
            float2 x02 = *(const float2*)(r0p + c0 + 8);
            float2 x10 = *(const float2*)(r1p + c0);
            float2 x12 = *(const float2*)(r1p + c0 + 8);
            cvt_hilo2(x00.x*0.125f, x00.y*0.125f, ah[ks][0], al[ks][0]);
            cvt_hilo2(x10.x*0.125f, x10.y*0.125f, ah[ks][1], al[ks][1]);
            cvt_hilo2(x02.x*0.125f, x02.y*0.125f, ah[ks][2], al[ks][2]);
            cvt_hilo2(x12.x*0.125f, x12.y*0.125f, ah[ks][3], al[ks][3]);
        }
    }

    // K staging identity: key = t>>2 (0..63), 16-float quarter = t&3 (coalesced LDG)
    const int kkey = t >> 2, kqtr = t & 3;
    const float* ksrc = kb + (size_t)kkey*DD + kqtr*16;
    const int koff = kkey*144 + kqtr*32;

    float4 kraw[4];
    #pragma unroll
    for (int ch = 0; ch < 4; ++ch) kraw[ch] = ((const float4*)ksrc)[ch];

    // prologue: stage tile 0 into buf0
    {
        char* khi = sm;  char* klo = sm + 9216;
        uint32_t hh[8], ll[8];
        cvt_hilo2(kraw[0].x,kraw[0].y,hh[0],ll[0]); cvt_hilo2(kraw[0].z,kraw[0].w,hh[1],ll[1]);
        cvt_hilo2(kraw[1].x,kraw[1].y,hh[2],ll[2]); cvt_hilo2(kraw[1].z,kraw[1].w,hh[3],ll[3]);
        cvt_hilo2(kraw[2].x,kraw[2].y,hh[4],ll[4]); cvt_hilo2(kraw[2].z,kraw[2].w,hh[5],ll[5]);
        cvt_hilo2(kraw[3].x,kraw[3].y,hh[6],ll[6]); cvt_hilo2(kraw[3].z,kraw[3].w,hh[7],ll[7]);
        *(uint4*)(khi + koff)      = make_uint4(hh[0],hh[1],hh[2],hh[3]);
        *(uint4*)(khi + koff + 16) = make_uint4(hh[4],hh[5],hh[6],hh[7]);
        *(uint4*)(klo + koff)      = make_uint4(ll[0],ll[1],ll[2],ll[3]);
        *(uint4*)(klo + koff + 16) = make_uint4(ll[4],ll[5],ll[6],ll[7]);
    }
    __syncthreads();

    float m0 = -3.4e38f, s0 = 0.f, m1 = -3.4e38f, s1 = 0.f;

    for (int j = 0; j < 32; ++j) {
        // prefetch next K tile (flies during MMA phase)
        if (j + 1 < 32) {
            const float* nsrc = ksrc + (size_t)(j+1)*64*DD;
            #pragma unroll
            for (int ch = 0; ch < 4; ++ch) kraw[ch] = ((const float4*)nsrc)[ch];
        }

        // ---- MMA phase on buf[j&1] ----
        {
            char* khi = sm + (j&1)*A_BUF;
            char* klo = khi + 9216;
            float2 bi0 = *(const float2*)(bbp + (size_t)lr*TT + j*64 + qd*2);
            float2 bi1 = *(const float2*)(bbp + (size_t)(lr+8)*TT + j*64 + qd*2);
            #pragma unroll
            for (int n = 0; n < 8; ++n) {
                float2 nbi0, nbi1;
                if (n + 1 < 8) {
                    const int cn = j*64 + (n+1)*8 + qd*2;
                    nbi0 = *(const float2*)(bbp + (size_t)lr*TT + cn);
                    nbi1 = *(const float2*)(bbp + (size_t)(lr+8)*TT + cn);
                }
                float4 d = make_float4(0.f, 0.f, 0.f, 0.f);
                const char* bhp = khi + (n*8 + g)*144 + qd*4;
                const char* blp = klo + (n*8 + g)*144 + qd*4;
                #pragma unroll
                for (int ks = 0; ks < 4; ++ks) {
                    uint32_t bh0 = *(const uint32_t*)(bhp + ks*32);
                    uint32_t bh1 = *(const uint32_t*)(bhp + ks*32 + 16);
                    uint32_t bl0 = *(const uint32_t*)(blp + ks*32);
                    uint32_t bl1 = *(const uint32_t*)(blp + ks*32 + 16);
                    mma16816(d, ah[ks], bh0, bh1);
                    mma16816(d, al[ks], bh0, bh1);
                    mma16816(d, ah[ks], bl0, bl1);
                }
                const int c = j*64 + n*8 + qd*2;
                int2 mv = *(const int2*)&s_mask[c];
                float v00 = mv.x ? d.x + bi0.x : -1e9f;
                float v01 = mv.y ? d.y + bi0.y : -1e9f;
                float v10 = mv.x ? d.z + bi1.x : -1e9f;
                float v11 = mv.y ? d.w + bi1.y : -1e9f;
                *(float2*)(ab + (size_t)lr*TT + c)     = make_float2(v00, v01);
                *(float2*)(ab + (size_t)(lr+8)*TT + c) = make_float2(v10, v11);
                float nm0 = fmaxf(m0, fmaxf(v00, v01));
                s0 = s0*__expf(m0 - nm0) + __expf(v00 - nm0) + __expf(v01 - nm0);
                m0 = nm0;
                float nm1 = fmaxf(m1, fmaxf(v10, v11));
                s1 = s1*__expf(m1 - nm1) + __expf(v10 - nm1) + __expf(v11 - nm1);
                m1 = nm1;
                bi0 = nbi0; bi1 = nbi1;
            }
        }

        // ---- stage tile j+1 into buf[(j+1)&1] (overlaps other warps' MMAs) ----
        if (j + 1 < 32) {
            char* khi = sm + ((j+1)&1)*A_BUF;
            char* klo = khi + 9216;
            uint32_t hh[8], ll[8];
            cvt_hilo2(kraw[0].x,kraw[0].y,hh[0],ll[0]); cvt_hilo2(kraw[0].z,kraw[0].w,hh[1],ll[1]);
            cvt_hilo2(kraw[1].x,kraw[1].y,hh[2],ll[2]); cvt_hilo2(kraw[1].z,kraw[1].w,hh[3],ll[3]);
            cvt_hilo2(kraw[2].x,kraw[2].y,hh[4],ll[4]); cvt_hilo2(kraw[2].z,kraw[2].w,hh[5],ll[5]);
            cvt_hilo2(kraw[3].x,kraw[3].y,hh[6],ll[6]); cvt_hilo2(kraw[3].z,kraw[3].w,hh[7],ll[7]);
            *(uint4*)(khi + koff)      = make_uint4(hh[0],hh[1],hh[2],hh[3]);
            *(uint4*)(khi + koff + 16) = make_uint4(hh[4],hh[5],hh[6],hh[7]);
            *(uint4*)(klo + koff)      = make_uint4(ll[0],ll[1],ll[2],ll[3]);
            *(uint4*)(klo + koff + 16) = make_uint4(ll[4],ll[5],ll[6],ll[7]);
        }
        __syncthreads();
    }

    #pragma unroll
    for (int o = 1; o < 4; o <<= 1) {
        float mo = __shfl_xor_sync(0xffffffffu, m0, o);
        float so = __shfl_xor_sync(0xffffffffu, s0, o);
        float nm = fmaxf(m0, mo);
        s0 = s0*__expf(m0 - nm) + so*__expf(mo - nm); m0 = nm;
        mo = __shfl_xor_sync(0xffffffffu, m1, o);
        so = __shfl_xor_sync(0xffffffffu, s1, o);
        nm = fmaxf(m1, mo);
        s1 = s1*__expf(m1 - nm) + so*__expf(mo - nm); m1 = nm;
    }
    if (qd == 0) {
        const size_t gi = (size_t)(b*HH + h)*TT + q0;
        g_m[gi + lr]       = m0;  g_inv[gi + lr]     = 1.f/s0;
        g_m[gi + lr + 8]   = m1;  g_inv[gi + lr + 8] = 1.f/s1;
    }
}

// ==================== Kernel B: PV, double-buffered 32-key tiles ====================
// buf: PHI 128*72=9216 | PLO 9216 | VHI 64*72=4608 | VLO 4608 => 27648/buf; x2 = 55296; stat 1024
#define B_BUF 27648
#define B_PST 72
#define B_VST 72
#define B_STAT 55296
#define B_TOTAL 56320

__global__ __launch_bounds__(256, 2)
void pv_mma(const float* __restrict__ gv, float* __restrict__ gattn,
            float* __restrict__ gout)
{
    extern __shared__ char sm[];
    float2* s_stat = (float2*)(sm + B_STAT);

    const int t = threadIdx.x, wid = t >> 5, lane = t & 31;
    const int h = blockIdx.y, b = blockIdx.z;
    const int q0 = blockIdx.x * 128;
    const int g = lane >> 2, qd = lane & 3;
    const int lr = wid*16 + g;

    const float* vb = gv + ((size_t)(b*HH + h))*TT*DD;
    float*       ab = gattn + (((size_t)(b*HH + h))*TT + q0)*TT;
    const size_t st = (size_t)(b*HH + h)*TT + q0;

    if (t < 128) s_stat[t] = make_float2(g_m[st + t], g_inv[st + t]);

    // P staging map: rows r = wid*16 + rp*4 + (lane>>3), col = (lane&7)*4 (coalesced)
    const int prl = lane >> 3;          // 0..3
    const int pcol = (lane & 7) * 4;    // float4 col in 32-key tile
    // V staging map: key-pair kp = t&15, d-quad dq = t>>4 (0..15)
    const int vkp = t & 15, vdq = t >> 4;

    float4 o[8];
    #pragma unroll
    for (int i = 0; i < 8; ++i) o[i] = make_float4(0.f, 0.f, 0.f, 0.f);

    float4 praw[4];
    float4 vraw[2];
    // prefetch tile 0
    #pragma unroll
    for (int rp = 0; rp < 4; ++rp) {
        const int r = wid*16 + rp*4 + prl;
        praw[rp] = *(const float4*)(ab + (size_t)r*TT + pcol);
    }
    {
        const float* v0 = vb + (size_t)(2*vkp)*DD + vdq*4;
        vraw[0] = *(const float4*)v0;
        vraw[1] = *(const float4*)(v0 + DD);
    }
    __syncthreads();   // s_stat visible

    // prologue: stage tile 0 into buf0
    {
        char* phi = sm;            char* plo = sm + 9216;
        char* vhi = sm + 18432;    char* vlo = sm + 23040;
        #pragma unroll
        for (int rp = 0; rp < 4; ++rp) {
            const int r = wid*16 + rp*4 + prl;
            const float2 ms = s_stat[r];
            float4 x = praw[rp];
            x.x = __expf(x.x - ms.x)*ms.y;  x.y = __expf(x.y - ms.x)*ms.y;
            x.z = __expf(x.z - ms.x)*ms.y;  x.w = __expf(x.w - ms.x)*ms.y;
            *(float4*)(ab + (size_t)r*TT + pcol) = x;
            uint32_t h0,l0,h1,l1;
            cvt_hilo2(x.x, x.y, h0, l0);
            cvt_hilo2(x.z, x.w, h1, l1);
            *(uint2*)(phi + r*B_PST + pcol*2) = make_uint2(h0, h1);
            *(uint2*)(plo + r*B_PST + pcol*2) = make_uint2(l0, l1);
        }
        #pragma unroll
        for (int u = 0; u < 4; ++u) {
            float x = (u==0)?vraw[0].x:(u==1)?vraw[0].y:(u==2)?vraw[0].z:vraw[0].w;
            float y = (u==0)?vraw[1].x:(u==1)?vraw[1].y:(u==2)?vraw[1].z:vraw[1].w;
            uint32_t hp, lp;
            cvt_hilo2(x, y, hp, lp);
            *(uint32_t*)(vhi + (vdq*4 + u)*B_VST + vkp*4) = hp;
            *(uint32_t*)(vlo + (vdq*4 + u)*B_VST + vkp*4) = lp;
        }
    }
    __syncthreads();

    for (int j = 0; j < 64; ++j) {
        // prefetch tile j+1 (flies during MMA)
        if (j + 1 < 64) {
            #pragma unroll
            for (int rp = 0; rp < 4; ++rp) {
                const int r = wid*16 + rp*4 + prl;
                praw[rp] = *(const float4*)(ab + (size_t)r*TT + (j+1)*32 + pcol);
            }
            const float* v0 = vb + (size_t)((j+1)*32 + 2*vkp)*DD + vdq*4;
            vraw[0] = *(const float4*)v0;
            vraw[1] = *(const float4*)(v0 + DD);
        }

        // ---- MMA phase on buf[j&1] ----
        {
            char* phi = sm + (j&1)*B_BUF;  char* plo = phi + 9216;
            char* vhi = phi + 18432;       char* vlo = phi + 23040;
            #pragma unroll
            for (int kst = 0; kst < 2; ++kst) {
                const int abase = lr*B_PST + kst*32 + qd*4;
                uint32_t ph[4], pl[4];
                ph[0] = *(const uint32_t*)(phi + abase);
                ph[1] = *(const uint32_t*)(phi + abase + 8*B_PST);
                ph[2] = *(const uint32_t*)(phi + abase + 16);
                ph[3] = *(const uint32_t*)(phi + abase + 8*B_PST + 16);
                pl[0] = *(const uint32_t*)(plo + abase);
                pl[1] = *(const uint32_t*)(plo + abase + 8*B_PST);
                pl[2] = *(const uint32_t*)(plo + abase + 16);
                pl[3] = *(const uint32_t*)(plo + abase + 8*B_PST + 16);
                #pragma unroll
                for (int ns = 0; ns < 8; ++ns) {
                    const int bbase = (ns*8 + g)*B_VST + kst*32 + qd*4;
                    uint32_t bh0 = *(const uint32_t*)(vhi + bbase);
                    uint32_t bh1 = *(const uint32_t*)(vhi + bbase + 16);
                    uint32_t bl0 = *(const uint32_t*)(vlo + bbase);
                    uint32_t bl1 = *(const uint32_t*)(vlo + bbase + 16);
                    mma16816(o[ns], ph, bh0, bh1);
                    mma16816(o[ns], pl, bh0, bh1);
                    mma16816(o[ns], ph, bl0, bl1);
                }
            }
        }

        // ---- stage tile j+1 into buf[(j+1)&1] ----
        if (j + 1 < 64) {
            char* phi = sm + ((j+1)&1)*B_BUF;  char* plo = phi + 9216;
            char* vhi = phi + 18432;           char* vlo = phi + 23040;
            #pragma unroll
            for (int rp = 0; rp < 4; ++rp) {
                const int r = wid*16 + rp*4 + prl;
                const float2 ms = s_stat[r];
                float4 x = praw[rp];
                x.x = __expf(x.x - ms.x)*ms.y;  x.y = __expf(x.y - ms.x)*ms.y;
                x.z = __expf(x.z - ms.x)*ms.y;  x.w = __expf(x.w - ms.x)*ms.y;
                *(float4*)(ab + (size_t)r*TT + (j+1)*32 + pcol) = x;
                uint32_t h0,l0,h1,l1;
                cvt_hilo2(x.x, x.y, h0, l0);
                cvt_hilo2(x.z, x.w, h1, l1);
                *(uint2*)(phi + r*B_PST + pcol*2) = make_uint2(h0, h1);
                *(uint2*)(plo + r*B_PST + pcol*2) = make_uint2(l0, l1);
            }
            #pragma unroll
            for (int u = 0; u < 4; ++u) {
                float x = (u==0)?vraw[0].x:(u==1)?vraw[0].y:(u==2)?vraw[0].z:vraw[0].w;
                float y = (u==0)?vraw[1].x:(u==1)?vraw[1].y:(u==2)?vraw[1].z:vraw[1].w;
                uint32_t hp, lp;
                cvt_hilo2(x, y, hp, lp);
                *(uint32_t*)(vhi + (vdq*4 + u)*B_VST + vkp*4) = hp;
                *(uint32_t*)(vlo + (vdq*4 + u)*B_VST + vkp*4) = lp;
            }
        }
        __syncthreads();
    }

    float* ob = gout + (((size_t)(b*HH + h))*TT + q0)*DD;
    #pragma unroll
    for (int ns = 0; ns < 8; ++ns) {
        const int c = ns*8 + qd*2;
        *(float2*)(ob + (size_t)lr*DD + c)     = make_float2(o[ns].x, o[ns].y);
        *(float2*)(ob + (size_t)(lr+8)*DD + c) = make_float2(o[ns].z, o[ns].w);
    }
}

extern "C" void kernel_launch(void* const* d_in, const int* in_sizes, int n_in,
                              void* d_out, int out_size)
{
    const float* q    = (const float*)d_in[0];
    const float* k    = (const float*)d_in[1];
    const float* v    = (const float*)d_in[2];
    const int*   mask = (const int*)d_in[3];
    const float* bias = (const float*)d_in[4];
    float* out  = (float*)d_out;
    float* attn = out + (long long)BB*HH*TT*DD;

    cudaFuncSetAttribute(qk_mma, cudaFuncAttributeMaxDynamicSharedMemorySize, A_TOTAL);
    cudaFuncSetAttribute(pv_mma, cudaFuncAttributeMaxDynamicSharedMemorySize, B_TOTAL);

    dim3 grid(TT/128, HH, BB);
    qk_mma<<<grid, 256, A_TOTAL>>>(q, k, mask, bias, attn);
    pv_mma<<<grid, 256, B_TOTAL>>>(v, attn, out);
}

// round 16
// speedup vs baseline: 1.2835x; 1.0859x over previous
#include <cuda_runtime.h>
#include <cuda_bf16.h>
#include <stdint.h>

#define TT 2048
#define DD 64
#define HH 16
#define BB 2

__device__ __forceinline__ void mma16816(float4& d, const uint32_t* a,
                                         uint32_t b0, uint32_t b1) {
    asm volatile("mma.sync.aligned.m16n8k16.row.col.f32.bf16.bf16.f32 "
        "{%0,%1,%2,%3}, {%4,%5,%6,%7}, {%8,%9}, {%0,%1,%2,%3};"
        : "+f"(d.x), "+f"(d.y), "+f"(d.z), "+f"(d.w)
        : "r"(a[0]), "r"(a[1]), "r"(a[2]), "r"(a[3]), "r"(b0), "r"(b1));
}
__device__ __forceinline__ void cvt_hilo2(float x, float y, uint32_t& hi, uint32_t& lo) {
    __nv_bfloat162 hb = __floats2bfloat162_rn(x, y);
    __nv_bfloat162 lb = __floats2bfloat162_rn(x - __bfloat162float(hb.x),
                                              y - __bfloat162float(hb.y));
    hi = *reinterpret_cast<uint32_t*>(&hb);
    lo = *reinterpret_cast<uint32_t*>(&lb);
}

// ==================== Merged kernel: QK stats pass + PV pass, one CTA ====================
// pass1 smem: KHI 0..18431 | KLO 18432..36863 | MASK 36864..45055
// pass2 smem: PHI 0..18431 | PLO 18432..36863 | VHI 36864..46079 | VLO 46080..55295
// stats:      STAT 55296..56319  (float2[128])
#define P1_KHI 0
#define P1_KLO 18432
#define P1_MASK 36864
#define P2_PHI 0
#define P2_PLO 18432
#define P2_VHI 36864
#define P2_VLO 46080
#define S_STAT 55296
#define M_TOTAL 56320
#define PSTRIDE 144
#define VSTRIDE 144

__global__ __launch_bounds__(256, 2)
void attn_mma(const float* __restrict__ gq, const float* __restrict__ gk,
              const float* __restrict__ gv, const int* __restrict__ gmask,
              const float* __restrict__ gbias, float* __restrict__ gattn,
              float* __restrict__ gout)
{
    extern __shared__ char sm[];
    const int t = threadIdx.x, wid = t >> 5, lane = t & 31;
    const int h = blockIdx.y, b = blockIdx.z;
    const int q0 = blockIdx.x * 128;
    const int g = lane >> 2, qd = lane & 3;
    const int lr = wid*16 + g;

    const float* qb = gq + (((size_t)(b*HH + h))*TT + q0)*DD;
    const float* kb = gk + ((size_t)(b*HH + h))*TT*DD;
    const float* vb = gv + ((size_t)(b*HH + h))*TT*DD;
    const float* bbp = gbias + ((size_t)h*TT + q0)*TT;
    float*       ab = gattn + (((size_t)(b*HH + h))*TT + q0)*TT;

    // =============== PASS 1: QK^T -> raw scores + per-row (m, 1/sum) ===============
    {
        char* s_khi = sm + P1_KHI;
        char* s_klo = sm + P1_KLO;
        int*  s_mask = (int*)(sm + P1_MASK);

        ((int4*)s_mask)[t*2]   = ((const int4*)(gmask + b*TT))[t*2];
        ((int4*)s_mask)[t*2+1] = ((const int4*)(gmask + b*TT))[t*2+1];

        // Q frags (scale folded)
        uint32_t ah[4][4], al[4][4];
        {
            const float* r0p = qb + (size_t)lr*DD;
            const float* r1p = qb + (size_t)(lr+8)*DD;
            #pragma unroll
            for (int ks = 0; ks < 4; ++ks) {
                const int c0 = ks*16 + qd*2;
                float2 x00 = *(const float2*)(r0p + c0);
                float2 x02 = *(const float2*)(r0p + c0 + 8);
                float2 x10 = *(const float2*)(r1p + c0);
                float2 x12 = *(const float2*)(r1p + c0 + 8);
                cvt_hilo2(x00.x*0.125f, x00.y*0.125f, ah[ks][0], al[ks][0]);
                cvt_hilo2(x10.x*0.125f, x10.y*0.125f, ah[ks][1], al[ks][1]);
                cvt_hilo2(x02.x*0.125f, x02.y*0.125f, ah[ks][2], al[ks][2]);
                cvt_hilo2(x12.x*0.125f, x12.y*0.125f, ah[ks][3], al[ks][3]);
            }
        }

        const int key = t >> 1, half = t & 1;
        const float* ksrc = kb + (size_t)key*DD + half*32;

        float4 kraw[8];
        #pragma unroll
        for (int ch = 0; ch < 8; ++ch) kraw[ch] = ((const float4*)ksrc)[ch];

        float m0 = -3.4e38f, s0 = 0.f, m1 = -3.4e38f, s1 = 0.f;

        for (int j = 0; j < 16; ++j) {
            __syncthreads();
            #pragma unroll
            for (int ch = 0; ch < 4; ++ch) {
                float4 a = kraw[2*ch];
                float4 c = kraw[2*ch+1];
                uint32_t h0,l0,h1,l1,h2,l2,h3,l3;
                cvt_hilo2(a.x,a.y,h0,l0); cvt_hilo2(a.z,a.w,h1,l1);
                cvt_hilo2(c.x,c.y,h2,l2); cvt_hilo2(c.z,c.w,h3,l3);
                const int off = key*144 + half*64 + ch*16;
                *(uint4*)(s_khi + off) = make_uint4(h0,h1,h2,h3);
                *(uint4*)(s_klo + off) = make_uint4(l0,l1,l2,l3);
            }
            __syncthreads();

            if (j + 1 < 16) {
                const float* nsrc = ksrc + (size_t)(j+1)*128*DD;
                #pragma unroll
                for (int ch = 0; ch < 8; ++ch) kraw[ch] = ((const float4*)nsrc)[ch];
            }

            float2 bi0 = *(const float2*)(bbp + (size_t)lr*TT + j*128 + qd*2);
            float2 bi1 = *(const float2*)(bbp + (size_t)(lr+8)*TT + j*128 + qd*2);

            #pragma unroll 2
            for (int n = 0; n < 16; ++n) {
                float2 nbi0, nbi1;
                if (n + 1 < 16) {
                    const int cn = j*128 + (n+1)*8 + qd*2;
                    nbi0 = *(const float2*)(bbp + (size_t)lr*TT + cn);
                    nbi1 = *(const float2*)(bbp + (size_t)(lr+8)*TT + cn);
                }
                float4 d = make_float4(0.f, 0.f, 0.f, 0.f);
                const char* bhp = s_khi + (n*8 + g)*144 + qd*4;
                const char* blp = s_klo + (n*8 + g)*144 + qd*4;
                #pragma unroll
                for (int ks = 0; ks < 4; ++ks) {
                    uint32_t bh0 = *(const uint32_t*)(bhp + ks*32);
                    uint32_t bh1 = *(const uint32_t*)(bhp + ks*32 + 16);
                    uint32_t bl0 = *(const uint32_t*)(blp + ks*32);
                    uint32_t bl1 = *(const uint32_t*)(blp + ks*32 + 16);
                    mma16816(d, ah[ks], bh0, bh1);
                    mma16816(d, al[ks], bh0, bh1);
                    mma16816(d, ah[ks], bl0, bl1);
                }
                const int c = j*128 + n*8 + qd*2;
                int2 mv = *(const int2*)&s_mask[c];
                float v00 = mv.x ? d.x + bi0.x : -1e9f;
                float v01 = mv.y ? d.y + bi0.y : -1e9f;
                float v10 = mv.x ? d.z + bi1.x : -1e9f;
                float v11 = mv.y ? d.w + bi1.y : -1e9f;
                *(float2*)(ab + (size_t)lr*TT + c)     = make_float2(v00, v01);
                *(float2*)(ab + (size_t)(lr+8)*TT + c) = make_float2(v10, v11);
                float nm0 = fmaxf(m0, fmaxf(v00, v01));
                s0 = s0*__expf(m0 - nm0) + __expf(v00 - nm0) + __expf(v01 - nm0);
                m0 = nm0;
                float nm1 = fmaxf(m1, fmaxf(v10, v11));
                s1 = s1*__expf(m1 - nm1) + __expf(v10 - nm1) + __expf(v11 - nm1);
                m1 = nm1;
                bi0 = nbi0; bi1 = nbi1;
            }
        }

        #pragma unroll
        for (int o = 1; o < 4; o <<= 1) {
            float mo = __shfl_xor_sync(0xffffffffu, m0, o);
            float so = __shfl_xor_sync(0xffffffffu, s0, o);
            float nm = fmaxf(m0, mo);
            s0 = s0*__expf(m0 - nm) + so*__expf(mo - nm); m0 = nm;
            mo = __shfl_xor_sync(0xffffffffu, m1, o);
            so = __shfl_xor_sync(0xffffffffu, s1, o);
            nm = fmaxf(m1, mo);
            s1 = s1*__expf(m1 - nm) + so*__expf(mo - nm); m1 = nm;
        }
        float2* s_stat = (float2*)(sm + S_STAT);
        if (qd == 0) {
            s_stat[lr]     = make_float2(m0, 1.f/s0);
            s_stat[lr + 8] = make_float2(m1, 1.f/s1);
        }
    }

    __syncthreads();   // phase barrier: pass-1 smem reads done, stats visible

    // =============== PASS 2: normalize -> attn + PV -> out ===============
    {
        char* s_phi = sm + P2_PHI;
        char* s_plo = sm + P2_PLO;
        char* s_vhi = sm + P2_VHI;
        char* s_vlo = sm + P2_VLO;
        float2* s_stat = (float2*)(sm + S_STAT);

        const int hl = lane >> 4;
        const int lc = (lane & 15) * 4;
        const int vkp = lane, vdq = wid;

        float4 o[8];
        #pragma unroll
        for (int i = 0; i < 8; ++i) o[i] = make_float4(0.f, 0.f, 0.f, 0.f);

        float4 praw[8];
        #pragma unroll
        for (int rp = 0; rp < 8; ++rp) {
            const int r = wid*16 + rp*2 + hl;
            praw[rp] = *(const float4*)(ab + (size_t)r*TT + lc);
        }

        for (int j = 0; j < 32; ++j) {
            __syncthreads();
            #pragma unroll
            for (int rp = 0; rp < 8; ++rp) {
                const int r = wid*16 + rp*2 + hl;
                const float2 ms = s_stat[r];
                float4 x = praw[rp];
                x.x = __expf(x.x - ms.x)*ms.y;
                x.y = __expf(x.y - ms.x)*ms.y;
                x.z = __expf(x.z - ms.x)*ms.y;
                x.w = __expf(x.w - ms.x)*ms.y;
                *(float4*)(ab + (size_t)r*TT + j*64 + lc) = x;
                uint32_t h0,l0,h1,l1;
                cvt_hilo2(x.x, x.y, h0, l0);
                cvt_hilo2(x.z, x.w, h1, l1);
                const int off = r*PSTRIDE + lc*2;
                *(uint2*)(s_phi + off) = make_uint2(h0, h1);
                *(uint2*)(s_plo + off) = make_uint2(l0, l1);
            }
            {
                const float* v0 = vb + (size_t)(j*64 + 2*vkp)*DD + vdq*8;
                float4 a0 = *(const float4*)v0;
                float4 a1 = *(const float4*)(v0 + 4);
                float4 c0 = *(const float4*)(v0 + DD);
                float4 c1 = *(const float4*)(v0 + DD + 4);
                #pragma unroll
                for (int u = 0; u < 4; ++u) {
                    float x = (u==0)?a0.x:(u==1)?a0.y:(u==2)?a0.z:a0.w;
                    float y = (u==0)?c0.x:(u==1)?c0.y:(u==2)?c0.z:c0.w;
                    uint32_t hp, lp;
                    cvt_hilo2(x, y, hp, lp);
                    const int off = (vdq*8 + u)*VSTRIDE + vkp*4;
                    *(uint32_t*)(s_vhi + off) = hp;
                    *(uint32_t*)(s_vlo + off) = lp;
                }
                #pragma unroll
                for (int u = 0; u < 4; ++u) {
                    float x = (u==0)?a1.x:(u==1)?a1.y:(u==2)?a1.z:a1.w;
                    float y = (u==0)?c1.x:(u==1)?c1.y:(u==2)?c1.z:c1.w;
                    uint32_t hp, lp;
                    cvt_hilo2(x, y, hp, lp);
                    const int off = (vdq*8 + 4 + u)*VSTRIDE + vkp*4;
                    *(uint32_t*)(s_vhi + off) = hp;
                    *(uint32_t*)(s_vlo + off) = lp;
                }
            }
            __syncthreads();

            if (j + 1 < 32) {
                #pragma unroll
                for (int rp = 0; rp < 8; ++rp) {
                    const int r = wid*16 + rp*2 + hl;
                    praw[rp] = *(const float4*)(ab + (size_t)r*TT + (j+1)*64 + lc);
                }
            }

            #pragma unroll
            for (int kst = 0; kst < 4; ++kst) {
                const int abase = lr*PSTRIDE + kst*32 + qd*4;
                uint32_t ph[4], pl[4];
                ph[0] = *(const uint32_t*)(s_phi + abase);
                ph[1] = *(const uint32_t*)(s_phi + abase + 8*PSTRIDE);
                ph[2] = *(const uint32_t*)(s_phi + abase + 16);
                ph[3] = *(const uint32_t*)(s_phi + abase + 8*PSTRIDE + 16);
                pl[0] = *(const uint32_t*)(s_plo + abase);
                pl[1] = *(const uint32_t*)(s_plo + abase + 8*PSTRIDE);
                pl[2] = *(const uint32_t*)(s_plo + abase + 16);
                pl[3] = *(const uint32_t*)(s_plo + abase + 8*PSTRIDE + 16);
                #pragma unroll
                for (int ns = 0; ns < 8; ++ns) {
                    const int bbase = (ns*8 + g)*VSTRIDE + kst*32 + qd*4;
                    uint32_t bh0 = *(const uint32_t*)(s_vhi + bbase);
                    uint32_t bh1 = *(const uint32_t*)(s_vhi + bbase + 16);
                    uint32_t bl0 = *(const uint32_t*)(s_vlo + bbase);
                    uint32_t bl1 = *(const uint32_t*)(s_vlo + bbase + 16);
                    mma16816(o[ns], ph, bh0, bh1);
                    mma16816(o[ns], pl, bh0, bh1);
                    mma16816(o[ns], ph, bl0, bl1);
                }
            }
        }

        float* ob = gout + (((size_t)(b*HH + h))*TT + q0)*DD;
        #pragma unroll
        for (int ns = 0; ns < 8; ++ns) {
            const int c = ns*8 + qd*2;
            *(float2*)(ob + (size_t)lr*DD + c)     = make_float2(o[ns].x, o[ns].y);
            *(float2*)(ob + (size_t)(lr+8)*DD + c) = make_float2(o[ns].z, o[ns].w);
        }
    }
}

extern "C" void kernel_launch(void* const* d_in, const int* in_sizes, int n_in,
                              void* d_out, int out_size)
{
    const float* q    = (const float*)d_in[0];
    const float* k    = (const float*)d_in[1];
    const float* v    = (const float*)d_in[2];
    const int*   mask = (const int*)d_in[3];
    const float* bias = (const float*)d_in[4];
    float* out  = (float*)d_out;
    float* attn = out + (long long)BB*HH*TT*DD;

    cudaFuncSetAttribute(attn_mma, cudaFuncAttributeMaxDynamicSharedMemorySize, M_TOTAL);

    dim3 grid(TT/128, HH, BB);
    attn_mma<<<grid, 256, M_TOTAL>>>(q, k, v, mask, bias, attn, out);
}